// round 4
// baseline (speedup 1.0000x reference)
#include <cuda_runtime.h>

// SparseMCFModel — math reduction recap:
//  * decoder softmax has identical logits per segment => w[e] = 1/deg_row(row[e]) exactly.
//  * define y_t[r] = x_t[r]/deg_row[r]. Then:
//      x_{t+1}[n] = d_pos[n] + sum_{col(e)=n} y_t[row(e)]
//      y_{t+1}[n] = inv[n] * (d_pos[n] + sum_{col(e)=n} y_t[row(e)])
//      flow[e]    = y_10[row[e]]
//  * CSC built once (histogram tickets + scan + scatter) => iterations are
//    atomic-free: 1 random gather per edge, coalesced writes, 2-buffer ping-pong.

#define NN 20000
#define NE 200000
#define BS 256
#define CHUNK 128
#define NCHUNKS ((NN + CHUNK - 1) / CHUNK)   // 157

__device__ int   d_cntc[NN];     // in-degree by col (CSC counts)
__device__ int   d_cntr[NN];     // out-degree by row (weights)
__device__ int   d_offs[NN];     // CSC offsets (exclusive scan of cntc)
__device__ int   d_csum[NCHUNKS];
__device__ int   d_cbase[NCHUNKS];
__device__ int   d_tick[NE];     // per-edge ticket within its col bucket
__device__ int   d_srow[NE];     // CSC: source rows grouped by col
__device__ float d_y[2][NN];
__device__ float d_dpos[NN];
__device__ float d_inv[NN];

// ---- grid barrier: volatile-poll generation counter ----
__device__ unsigned int          g_count = 0;
__device__ volatile unsigned int g_gen   = 0;

__device__ __forceinline__ void grid_sync(unsigned int nblocks) {
    __syncthreads();
    if (threadIdx.x == 0) {
        __threadfence();
        unsigned int my = g_gen;
        unsigned int arrived = atomicAdd(&g_count, 1u);
        if (arrived == nblocks - 1u) {
            g_count = 0u;
            __threadfence();
            g_gen = my + 1u;
        } else {
            while (g_gen == my) { __nanosleep(32); }
        }
        __threadfence();
    }
    __syncthreads();
}

__global__ void __launch_bounds__(BS)
k_solve(const float* __restrict__ demands, const int* __restrict__ row,
        const int* __restrict__ col, float* __restrict__ out) {
    const unsigned int nb = gridDim.x;
    const int tid  = blockIdx.x * BS + threadIdx.x;
    const int T    = (int)nb * BS;
    const int lane = threadIdx.x & 31;
    const int gw   = tid >> 5;

    // 0: zero histograms
    for (int i = tid; i < NN; i += T) { d_cntc[i] = 0; d_cntr[i] = 0; }
    grid_sync(nb);

    // 1: histogram + tickets
    for (int e = tid; e < NE; e += T) {
        int c = __ldg(&col[e]);
        int r = __ldg(&row[e]);
        d_tick[e] = atomicAdd(&d_cntc[c], 1);
        atomicAdd(&d_cntr[r], 1);
    }
    grid_sync(nb);

    // 2: per-chunk sums (warp per chunk) + node init (inv, dpos, y_1)
    if (gw < NCHUNKS) {
        int base = gw * CHUNK + lane * 4;
        int s = 0;
#pragma unroll
        for (int j = 0; j < 4; j++) { int i = base + j; if (i < NN) s += d_cntc[i]; }
        for (int o = 16; o > 0; o >>= 1) s += __shfl_down_sync(0xffffffffu, s, o);
        if (lane == 0) d_csum[gw] = s;
    }
    for (int i = tid; i < NN; i += T) {
        int dr = d_cntr[i];
        float inv = dr ? (1.0f / (float)dr) : 0.0f;
        float dp = __ldg(&demands[i]);
        dp = dp > 0.0f ? dp : 0.0f;
        d_dpos[i] = dp;
        d_inv[i]  = inv;
        d_y[0][i] = inv * dp;                 // y_1
    }
    grid_sync(nb);

    // 3: scan chunk sums (block 0, warp 0; contiguous-per-lane layout)
    if (blockIdx.x == 0 && threadIdx.x < 32) {
        const int PER = (NCHUNKS + 31) / 32;  // 5
        int v[PER]; int s = 0;
#pragma unroll
        for (int j = 0; j < PER; j++) {
            int i = lane * PER + j;
            v[j] = (i < NCHUNKS) ? d_csum[i] : 0;
            s += v[j];
        }
        int inc = s;
        for (int o = 1; o < 32; o <<= 1) {
            int t2 = __shfl_up_sync(0xffffffffu, inc, o);
            if (lane >= o) inc += t2;
        }
        int run = inc - s;                    // exclusive base for this lane
#pragma unroll
        for (int j = 0; j < PER; j++) {
            int i = lane * PER + j;
            if (i < NCHUNKS) d_cbase[i] = run;
            run += v[j];
        }
    }
    grid_sync(nb);

    // 4: intra-chunk exclusive scan -> offs
    if (gw < NCHUNKS) {
        int base = gw * CHUNK + lane * 4;
        int v[4]; int s = 0;
#pragma unroll
        for (int j = 0; j < 4; j++) { int i = base + j; v[j] = (i < NN) ? d_cntc[i] : 0; s += v[j]; }
        int inc = s;
        for (int o = 1; o < 32; o <<= 1) {
            int t2 = __shfl_up_sync(0xffffffffu, inc, o);
            if (lane >= o) inc += t2;
        }
        int run = d_cbase[gw] + (inc - s);
#pragma unroll
        for (int j = 0; j < 4; j++) { int i = base + j; if (i < NN) d_offs[i] = run; run += v[j]; }
    }
    grid_sync(nb);

    // 5: ticketed scatter (plain stores, no atomics)
    for (int e = tid; e < NE; e += T) {
        int c = __ldg(&col[e]);
        d_srow[d_offs[c] + d_tick[e]] = __ldg(&row[e]);
    }
    grid_sync(nb);

    // 6: 9 atomic-free updates y_1 -> y_10
    int cur = 0;
#pragma unroll 1
    for (int t = 0; t < 9; t++) {
        int nxt = cur ^ 1;
        const float* __restrict__ yc = d_y[cur];
        float* __restrict__ yn = d_y[nxt];
        for (int n = tid; n < NN; n += T) {
            int b = d_offs[n];
            int end = b + d_cntc[n];
            float a0 = 0.f, a1 = 0.f, a2 = 0.f, a3 = 0.f;
            int j = b;
            for (; j + 4 <= end; j += 4) {
                int s0 = d_srow[j], s1 = d_srow[j + 1], s2 = d_srow[j + 2], s3 = d_srow[j + 3];
                a0 += yc[s0]; a1 += yc[s1]; a2 += yc[s2]; a3 += yc[s3];
            }
            for (; j < end; j++) a0 += yc[d_srow[j]];
            yn[n] = d_inv[n] * (d_dpos[n] + ((a0 + a1) + (a2 + a3)));
        }
        grid_sync(nb);
        cur = nxt;
    }

    // 7: flow[e] = y_10[row[e]]
    const float* __restrict__ yf = d_y[cur];
    for (int e = tid; e < NE; e += T)
        out[e] = yf[__ldg(&row[e])];
}

// ---------------- fallback multi-launch path (proven correct, 54us) ----------------
__device__ float g_dpos[NN];
__device__ float g_x[3][NN];
__device__ int   g_deg[NN];

__global__ void k_init(const float* __restrict__ demands) {
    int i = blockIdx.x * blockDim.x + threadIdx.x;
    if (i < NN) {
        float d = demands[i];
        d = d > 0.0f ? d : 0.0f;
        g_dpos[i] = d; g_x[0][i] = d; g_x[1][i] = d; g_deg[i] = 0;
    }
}
__global__ void k_deg(const int* __restrict__ row) {
    int e = blockIdx.x * blockDim.x + threadIdx.x;
    if (e < NE) atomicAdd(&g_deg[row[e]], 1);
}
__global__ void k_update(const int* __restrict__ row, const int* __restrict__ col,
                         int cur, int nxt, int rst) {
    int i = blockIdx.x * blockDim.x + threadIdx.x;
    if (i < NE) {
        int rr = __ldg(&row[i]);
        float ww = 1.0f / (float)g_deg[rr];
        atomicAdd(&g_x[nxt][__ldg(&col[i])], ww * g_x[cur][rr]);
    }
    if (i < NN) g_x[rst][i] = g_dpos[i];
}
__global__ void k_final(const int* __restrict__ row, float* __restrict__ out, int cur) {
    int e = blockIdx.x * blockDim.x + threadIdx.x;
    if (e < NE) {
        int rr = __ldg(&row[e]);
        out[e] = (1.0f / (float)g_deg[rr]) * g_x[cur][rr];
    }
}

extern "C" void kernel_launch(void* const* d_in, const int* in_sizes, int n_in,
                              void* d_out, int out_size) {
    const float* demands = (const float*)d_in[1];
    const int*   erow    = (const int*)d_in[2];
    const int*   ecol    = (const int*)d_in[3];
    float*       out     = (float*)d_out;

    static int coop_grid = -2;
    if (coop_grid == -2) {
        int dev = 0, nsm = 0, coop = 0, bpsm = 0;
        cudaGetDevice(&dev);
        cudaDeviceGetAttribute(&nsm,  cudaDevAttrMultiProcessorCount, dev);
        cudaDeviceGetAttribute(&coop, cudaDevAttrCooperativeLaunch,   dev);
        cudaOccupancyMaxActiveBlocksPerMultiprocessor(&bpsm, k_solve, BS, 0);
        int per_sm = bpsm < 2 ? bpsm : 2;     // 2 blocks/SM
        int g = nsm * per_sm;
        // need enough warps for the NCHUNKS warp-tasks
        if (!coop || g * (BS / 32) < NCHUNKS) coop_grid = -1;
        else coop_grid = g;
    }

    if (coop_grid > 0) {
        void* args[4] = { (void*)&demands, (void*)&erow, (void*)&ecol, (void*)&out };
        cudaError_t err = cudaLaunchCooperativeKernel(
            (void*)k_solve, dim3(coop_grid), dim3(BS), args, 0, 0);
        if (err == cudaSuccess) return;
        cudaGetLastError();
        coop_grid = -1;
    }

    // fallback
    const int gN = (NN + BS - 1) / BS;
    const int gE = (NE + BS - 1) / BS;
    k_init<<<gN, BS>>>(demands);
    k_deg<<<gE, BS>>>(erow);
    int cur = 0;
    for (int t = 0; t < 9; t++) {
        int nxt = (cur + 1) % 3, rst = (cur + 2) % 3;
        k_update<<<gE, BS>>>(erow, ecol, cur, nxt, rst);
        cur = nxt;
    }
    k_final<<<gE, BS>>>(erow, out, cur);
}

// round 5
// speedup vs baseline: 1.0571x; 1.0571x over previous
#include <cuda_runtime.h>

// SparseMCFModel — math reduction:
//  * decoder softmax has identical logits per segment => w[e] = 1/deg_row(row[e]) EXACTLY.
//  * node recurrence: x_1 = relu(demands);
//      x_{t+1}[n] = dpos[n] + sum_{e: col(e)=n} (1/deg[row(e)]) * x_t[row(e)]
//      flow[e]    = (1/deg[row(e)]) * x_10[row(e)]
//  * Edges sorted by ROW once (ticketed counting sort) =>
//      gather  x[row_sorted]  : coalesced/broadcast (~4 sectors/warp, not 32)
//      scatter atomicAdd(col) : random but fire-and-forget REDG (no return latency)
//  * 3-buffer rotation folds the dpos-reset into the iteration => 1 barrier/iter.

#define NN 20000
#define NE 200000
#define BS 512
#define MAXK 3
#define CHUNK 128
#define NCHUNKS ((NN + CHUNK - 1) / CHUNK)   // 157

__device__ int   d_cnt[NN];       // out-degree by row
__device__ int   d_offs[NN];      // CSR offsets
__device__ int   d_csum[NCHUNKS];
__device__ int   d_cbase[NCHUNKS];
__device__ int   d_tick[NE];
__device__ int   d_rows[NE];      // row id, sorted by row
__device__ int   d_cols[NE];      // col id, sorted by row
__device__ float d_x[3][NN];
__device__ float d_dpos[NN];
__device__ float d_inv[NN];
__device__ float d_z[NN];

// ---- grid barrier: single atomic arrival + volatile-poll release ----
__device__ unsigned int          g_count = 0;
__device__ volatile unsigned int g_gen   = 0;

__device__ __forceinline__ void grid_sync(unsigned int nblocks) {
    __syncthreads();
    if (threadIdx.x == 0) {
        __threadfence();
        unsigned int my = g_gen;
        unsigned int arrived = atomicAdd(&g_count, 1u);
        if (arrived == nblocks - 1u) {
            g_count = 0u;
            __threadfence();
            g_gen = my + 1u;
        } else {
            while (g_gen == my) { __nanosleep(32); }
        }
        __threadfence();
    }
    __syncthreads();
}

__global__ void __launch_bounds__(BS)
k_solve(const float* __restrict__ demands, const int* __restrict__ row,
        const int* __restrict__ col, float* __restrict__ out) {
    const unsigned int nb = gridDim.x;
    const int tid  = blockIdx.x * BS + threadIdx.x;
    const int T    = (int)nb * BS;
    const int lane = threadIdx.x & 31;
    const int gw   = tid >> 5;

    // P0: zero row histogram
    for (int i = tid; i < NN; i += T) d_cnt[i] = 0;
    grid_sync(nb);

    // P1: histogram by row + tickets
    for (int e = tid; e < NE; e += T)
        d_tick[e] = atomicAdd(&d_cnt[__ldg(&row[e])], 1);
    grid_sync(nb);

    // P2: per-chunk sums (warp per chunk) + node init (dpos, inv, x_1, pre-reset)
    if (gw < NCHUNKS) {
        int base = gw * CHUNK + lane * 4;
        int s = 0;
#pragma unroll
        for (int j = 0; j < 4; j++) { int i = base + j; if (i < NN) s += d_cnt[i]; }
        for (int o = 16; o > 0; o >>= 1) s += __shfl_down_sync(0xffffffffu, s, o);
        if (lane == 0) d_csum[gw] = s;
    }
    for (int i = tid; i < NN; i += T) {
        int dg = d_cnt[i];
        float dp = __ldg(&demands[i]);
        dp = dp > 0.0f ? dp : 0.0f;
        d_dpos[i] = dp;
        d_inv[i]  = dg ? (1.0f / (float)dg) : 0.0f;
        d_x[0][i] = dp;   // x_1
        d_x[1][i] = dp;   // first update target, pre-reset
    }
    grid_sync(nb);

    // P3: scan chunk sums (block 0, warp 0)
    if (blockIdx.x == 0 && threadIdx.x < 32) {
        const int PER = (NCHUNKS + 31) / 32;  // 5
        int v[PER]; int s = 0;
#pragma unroll
        for (int j = 0; j < PER; j++) {
            int i = lane * PER + j;
            v[j] = (i < NCHUNKS) ? d_csum[i] : 0;
            s += v[j];
        }
        int inc = s;
        for (int o = 1; o < 32; o <<= 1) {
            int t2 = __shfl_up_sync(0xffffffffu, inc, o);
            if (lane >= o) inc += t2;
        }
        int run = inc - s;
#pragma unroll
        for (int j = 0; j < PER; j++) {
            int i = lane * PER + j;
            if (i < NCHUNKS) d_cbase[i] = run;
            run += v[j];
        }
    }
    grid_sync(nb);

    // P4: intra-chunk exclusive scan -> offs
    if (gw < NCHUNKS) {
        int base = gw * CHUNK + lane * 4;
        int v[4]; int s = 0;
#pragma unroll
        for (int j = 0; j < 4; j++) { int i = base + j; v[j] = (i < NN) ? d_cnt[i] : 0; s += v[j]; }
        int inc = s;
        for (int o = 1; o < 32; o <<= 1) {
            int t2 = __shfl_up_sync(0xffffffffu, inc, o);
            if (lane >= o) inc += t2;
        }
        int run = d_cbase[gw] + (inc - s);
#pragma unroll
        for (int j = 0; j < 4; j++) { int i = base + j; if (i < NN) d_offs[i] = run; run += v[j]; }
    }
    grid_sync(nb);

    // P5: ticketed scatter -> edges sorted by row (plain stores)
    for (int e = tid; e < NE; e += T) {
        int r = __ldg(&row[e]);
        int p = d_offs[r] + d_tick[e];
        d_rows[p] = r;
        d_cols[p] = __ldg(&col[e]);
    }
    grid_sync(nb);

    // P6: register-cache my sorted edges (coalesced; weight gather near-coalesced)
    int   rr[MAXK], cc[MAXK];
    float wv[MAXK];
    bool  vl[MAXK];
#pragma unroll
    for (int k = 0; k < MAXK; k++) {
        int p = tid + k * T;
        vl[k] = (p < NE);
        rr[k] = vl[k] ? d_rows[p] : 0;
        cc[k] = vl[k] ? d_cols[p] : 0;
        wv[k] = vl[k] ? d_inv[rr[k]] : 0.0f;
    }

    // P7: 9 updates x_1 -> x_10 (gathers coalesced via row-sorted order)
    int cur = 0;
#pragma unroll 1
    for (int t = 0; t < 9; t++) {
        int nxt = cur + 1; if (nxt == 3) nxt = 0;
        int rst = nxt + 1; if (rst == 3) rst = 0;
        float xv[MAXK];
#pragma unroll
        for (int k = 0; k < MAXK; k++)
            xv[k] = vl[k] ? d_x[cur][rr[k]] : 0.0f;   // batched, MLP
#pragma unroll
        for (int k = 0; k < MAXK; k++)
            if (vl[k]) atomicAdd(&d_x[nxt][cc[k]], wv[k] * xv[k]);
        for (int i = tid; i < NN; i += T)
            d_x[rst][i] = d_dpos[i];                  // prep buffer for iter t+2
        grid_sync(nb);
        cur = nxt;
    }

    // P8: z[n] = inv[n] * x_10[n]
    for (int i = tid; i < NN; i += T)
        d_z[i] = d_inv[i] * d_x[cur][i];
    grid_sync(nb);

    // P9: out[e] = z[row[e]]  (original edge order)
    for (int e = tid; e < NE; e += T)
        out[e] = d_z[__ldg(&row[e])];
}

// ---------------- fallback multi-launch path (proven correct, 54us) ----------------
__device__ float g_dpos[NN];
__device__ float g_x[3][NN];
__device__ int   g_deg[NN];

__global__ void k_init(const float* __restrict__ demands) {
    int i = blockIdx.x * blockDim.x + threadIdx.x;
    if (i < NN) {
        float d = demands[i];
        d = d > 0.0f ? d : 0.0f;
        g_dpos[i] = d; g_x[0][i] = d; g_x[1][i] = d; g_deg[i] = 0;
    }
}
__global__ void k_deg(const int* __restrict__ row) {
    int e = blockIdx.x * blockDim.x + threadIdx.x;
    if (e < NE) atomicAdd(&g_deg[row[e]], 1);
}
__global__ void k_update(const int* __restrict__ row, const int* __restrict__ col,
                         int cur, int nxt, int rst) {
    int i = blockIdx.x * blockDim.x + threadIdx.x;
    if (i < NE) {
        int rq = __ldg(&row[i]);
        float ww = 1.0f / (float)g_deg[rq];
        atomicAdd(&g_x[nxt][__ldg(&col[i])], ww * g_x[cur][rq]);
    }
    if (i < NN) g_x[rst][i] = g_dpos[i];
}
__global__ void k_final(const int* __restrict__ row, float* __restrict__ out, int cur) {
    int e = blockIdx.x * blockDim.x + threadIdx.x;
    if (e < NE) {
        int rq = __ldg(&row[e]);
        out[e] = (1.0f / (float)g_deg[rq]) * g_x[cur][rq];
    }
}

extern "C" void kernel_launch(void* const* d_in, const int* in_sizes, int n_in,
                              void* d_out, int out_size) {
    const float* demands = (const float*)d_in[1];
    const int*   erow    = (const int*)d_in[2];
    const int*   ecol    = (const int*)d_in[3];
    float*       out     = (float*)d_out;

    static int coop_grid = -2;
    if (coop_grid == -2) {
        int dev = 0, nsm = 0, coop = 0, bpsm = 0;
        cudaGetDevice(&dev);
        cudaDeviceGetAttribute(&nsm,  cudaDevAttrMultiProcessorCount, dev);
        cudaDeviceGetAttribute(&coop, cudaDevAttrCooperativeLaunch,   dev);
        cudaOccupancyMaxActiveBlocksPerMultiprocessor(&bpsm, k_solve, BS, 0);
        int g = nsm;                              // 1 block/SM: fewest barrier arrivals
        bool ok = coop && bpsm >= 1 && g > 0 &&
                  (long long)g * BS * MAXK >= NE &&          // edge coverage
                  g * (BS / 32) >= NCHUNKS;                  // warp-task coverage
        coop_grid = ok ? g : -1;
    }

    if (coop_grid > 0) {
        void* args[4] = { (void*)&demands, (void*)&erow, (void*)&ecol, (void*)&out };
        cudaError_t err = cudaLaunchCooperativeKernel(
            (void*)k_solve, dim3(coop_grid), dim3(BS), args, 0, 0);
        if (err == cudaSuccess) return;
        cudaGetLastError();
        coop_grid = -1;
    }

    // fallback
    const int gN = (NN + 255) / 256;
    const int gE = (NE + 255) / 256;
    k_init<<<gN, 256>>>(demands);
    k_deg<<<gE, 256>>>(erow);
    int cur = 0;
    for (int t = 0; t < 9; t++) {
        int nxt = (cur + 1) % 3, rst = (cur + 2) % 3;
        k_update<<<gE, 256>>>(erow, ecol, cur, nxt, rst);
        cur = nxt;
    }
    k_final<<<gE, 256>>>(erow, out, cur);
}